// round 13
// baseline (speedup 1.0000x reference)
#include <cuda_runtime.h>
#include <cuda_fp16.h>
#include <math.h>
#include <stdint.h>

// Problem constants
#define NB 4
#define NN 8192
#define NC 1024
#define NH 128
#define TOTROWS 15360   // 8192 + 4096 + 2048 + 1024 scratch rows per batch

// Scratch (device globals)
__device__ __half g_qh[NB * NN * NH];
__device__ __half g_kh[NB * NN * NH];
__device__ __half g_vh[NB * NN * NH];
__device__ __half g_wth[3 * 128 * 1024];   // W^T [w][n][k] fp16
__device__ __half g_o[(size_t)NB * TOTROWS * NH];
__device__ float g_d[NB * TOTROWS];

// ============================ helpers ============================
__device__ __forceinline__ uint32_t smem_u32(const void* p) {
    uint32_t a;
    asm("{ .reg .u64 t; cvta.to.shared.u64 t, %1; cvt.u32.u64 %0, t; }"
        : "=r"(a) : "l"(p));
    return a;
}

__device__ __forceinline__ void ldsm_x4(uint32_t r[4], uint32_t addr) {
    asm volatile("ldmatrix.sync.aligned.m8n8.x4.shared.b16 {%0,%1,%2,%3}, [%4];"
                 : "=r"(r[0]), "=r"(r[1]), "=r"(r[2]), "=r"(r[3]) : "r"(addr));
}
__device__ __forceinline__ void ldsm_x4_t(uint32_t r[4], uint32_t addr) {
    asm volatile("ldmatrix.sync.aligned.m8n8.x4.trans.shared.b16 {%0,%1,%2,%3}, [%4];"
                 : "=r"(r[0]), "=r"(r[1]), "=r"(r[2]), "=r"(r[3]) : "r"(addr));
}

// D(+=) A@B : m16n8k16 fp16 -> f32
__device__ __forceinline__ void mma16816(float c[4], const uint32_t a[4],
                                         uint32_t b0, uint32_t b1) {
    asm volatile(
        "mma.sync.aligned.m16n8k16.row.col.f32.f16.f16.f32 "
        "{%0,%1,%2,%3}, {%4,%5,%6,%7}, {%8,%9}, {%0,%1,%2,%3};"
        : "+f"(c[0]), "+f"(c[1]), "+f"(c[2]), "+f"(c[3])
        : "r"(a[0]), "r"(a[1]), "r"(a[2]), "r"(a[3]), "r"(b0), "r"(b1));
}

// pack two f32 (even -> low half, odd -> high half) into fp16x2
__device__ __forceinline__ uint32_t pack_f16x2(float even, float odd) {
    uint32_t d;
    asm("cvt.rn.f16x2.f32 %0, %1, %2;" : "=r"(d) : "f"(odd), "f"(even));
    return d;
}
__device__ __forceinline__ uint32_t ex2_f16x2(uint32_t a) {
    uint32_t d;
    asm("ex2.approx.f16x2 %0, %1;" : "=r"(d) : "r"(a));
    return d;
}
__device__ __forceinline__ float ex2f(float x) {
    float r;
    asm("ex2.approx.f32 %0, %1;" : "=f"(r) : "f"(x));
    return r;
}

// cp.async helpers
__device__ __forceinline__ void cp16(uint32_t dst, const void* src) {
    asm volatile("cp.async.cg.shared.global [%0], [%1], 16;" :: "r"(dst), "l"(src));
}
__device__ __forceinline__ void cp_commit() {
    asm volatile("cp.async.commit_group;" ::: "memory");
}
template <int N>
__device__ __forceinline__ void cp_wait() {
    asm volatile("cp.async.wait_group %0;" :: "n"(N) : "memory");
}

// ---------------------------------------------------------------------------
// Kernel 0: transpose W (fp16) -> g_wth [w][n=128][k=1024]
// ---------------------------------------------------------------------------
__global__ __launch_bounds__(256) void split_w(
    const float* __restrict__ Wq, const float* __restrict__ Wk,
    const float* __restrict__ Wv)
{
    __shared__ float tile[32][33];
    const float* W = (blockIdx.z == 0) ? Wq : (blockIdx.z == 1) ? Wk : Wv;
    const int k0 = blockIdx.x * 32;
    const int n0 = blockIdx.y * 32;
    const int tx = threadIdx.x, ty = threadIdx.y;
    #pragma unroll
    for (int i = ty; i < 32; i += 8)
        tile[i][tx] = W[(size_t)(k0 + i) * NH + n0 + tx];
    __syncthreads();
    #pragma unroll
    for (int i = ty; i < 32; i += 8) {
        size_t idx = (size_t)blockIdx.z * 131072 + (size_t)(n0 + i) * 1024 + k0 + tx;
        g_wth[idx] = __float2half_rn(tile[tx][i]);
    }
}

// ---------------------------------------------------------------------------
// Kernel 1: QKV projection, 1-term fp16 mma.sync: D = xh @ Wh (fp32 accum).
// CTA tile M=128, N=128, K chunks of 32. grid=(256,3) y->Wq/Wk/Wv.
// B tile loaded coalesced (uint4) from pre-transposed g_wth.
// ---------------------------------------------------------------------------
#define PSTR 40                 // padded k stride (fp16 elements)
#define PBUF (128 * PSTR)       // elements per smem array
#define PROJ_SMEM_BYTES (2 * 2 * PBUF * 2)   // 2 buffers x {AH, BH}

__global__ __launch_bounds__(256) void proj_mma(const float* __restrict__ x)
{
    extern __shared__ __half psm[];
    const int t = threadIdx.x;
    const int lane = t & 31;
    const int wid = t >> 5;
    const int wm = wid & 1;
    const int wn = wid >> 1;
    const size_t m0 = (size_t)blockIdx.x * 128;
    const int wsel = blockIdx.y;
    const __half* wth = g_wth + (size_t)wsel * 131072;

    float acc[4][4][4];
    #pragma unroll
    for (int i = 0; i < 4; i++)
        #pragma unroll
        for (int j = 0; j < 4; j++)
            #pragma unroll
            for (int e = 0; e < 4; e++) acc[i][j][e] = 0.f;

    float4 sa[4];
    uint4 sbh[2];

    const int a_row[4] = { t >> 3, (t + 256) >> 3, (t + 512) >> 3, (t + 768) >> 3 };
    const int a_c4 = (t & 7) * 4;

    auto load_stage = [&](int k0) {
        #pragma unroll
        for (int p = 0; p < 4; p++)
            sa[p] = *(const float4*)&x[(m0 + a_row[p]) * NC + k0 + a_c4];
        #pragma unroll
        for (int p = 0; p < 2; p++) {
            int idx = t + p * 256;
            int row = idx >> 2, c8 = idx & 3;
            sbh[p] = *(const uint4*)&wth[(size_t)row * 1024 + k0 + c8 * 8];
        }
    };
    auto store_stage = [&](int buf) {
        __half* AH = psm + buf * 2 * PBUF;
        __half* BH = AH + PBUF;
        #pragma unroll
        for (int p = 0; p < 4; p++) {
            uint32_t h01 = pack_f16x2(sa[p].x, sa[p].y);
            uint32_t h23 = pack_f16x2(sa[p].z, sa[p].w);
            uint32_t off = a_row[p] * PSTR + a_c4;
            *(uint2*)&AH[off] = make_uint2(h01, h23);
        }
        #pragma unroll
        for (int p = 0; p < 2; p++) {
            int idx = t + p * 256;
            int row = idx >> 2, c8 = idx & 3;
            *(uint4*)&BH[row * PSTR + c8 * 8] = sbh[p];
        }
    };

    const uint32_t smbase = smem_u32(psm);
    const int lr = lane & 15;
    const int lc = (lane >> 4) * 8;

    auto compute = [&](int buf) {
        const uint32_t AHb = smbase + (buf * 2 * PBUF) * 2;
        const uint32_t BHb = AHb + PBUF * 2;
        #pragma unroll
        for (int ks = 0; ks < 2; ks++) {
            uint32_t ah[4][4];
            #pragma unroll
            for (int i = 0; i < 4; i++) {
                uint32_t off = ((wm * 64 + i * 16 + lr) * PSTR + ks * 16 + lc) * 2;
                ldsm_x4(ah[i], AHb + off);
            }
            #pragma unroll
            for (int jj = 0; jj < 2; jj++) {
                uint32_t off = ((wn * 32 + jj * 16 + lr) * PSTR + ks * 16 + lc) * 2;
                uint32_t bh[4];
                ldsm_x4(bh, BHb + off);
                #pragma unroll
                for (int i = 0; i < 4; i++) {
                    mma16816(acc[i][2 * jj],     ah[i], bh[0], bh[2]);
                    mma16816(acc[i][2 * jj + 1], ah[i], bh[1], bh[3]);
                }
            }
        }
    };

    load_stage(0);
    for (int c = 0; c < 32; c++) {
        store_stage(c & 1);
        __syncthreads();
        if (c + 1 < 32) load_stage((c + 1) * 32);
        compute(c & 1);
    }

    // epilogue: q pre-scaled by log2(e)/sqrt(128); single fp16 store
    const float scale = (wsel == 0) ? (0.08838834764831843f * 1.4426950408889634f) : 1.0f;
    __half* DH = (wsel == 0) ? g_qh : (wsel == 1) ? g_kh : g_vh;
    #pragma unroll
    for (int i = 0; i < 4; i++) {
        #pragma unroll
        for (int j = 0; j < 4; j++) {
            const int col = wn * 32 + j * 8 + 2 * (lane & 3);
            #pragma unroll
            for (int z = 0; z < 2; z++) {
                const size_t row = m0 + wm * 64 + i * 16 + (lane >> 2) + 8 * z;
                *(uint32_t*)&DH[row * NH + col] =
                    pack_f16x2(acc[i][j][2 * z] * scale, acc[i][j][2 * z + 1] * scale);
            }
        }
    }
}

// ---------------------------------------------------------------------------
// Kernel 2: causal flash attention, fp16 mma.sync, packed-fp16 exp2 softmax.
// QK 1-term, PV 1-term. 128-row Q tiles, 8 warps, cp.async double buffering.
// Warp-tile-granularity causal skipping only.
// cfg0 odd rows (= odd token positions, appearing in no other config) are
// normalized outputs with alpha==1 -> written DIRECTLY to out in fp32,
// bypassing g_o/g_d. All other rows go to g_o (fp16) + g_d as before.
// ---------------------------------------------------------------------------
#define ASTR 136                        // Q/K padded stride (fp16 elems)
#define VSTR 152                        // V padded stride (128 data + 16 ones/pad)
#define QTILE (128 * ASTR)              // 17408
#define KTILE (64 * ASTR)               // 8704
#define VTILE (64 * VSTR)               // 9728
#define BUFSZ (KTILE + VTILE)           // 18432 elems per buffer
#define ATTN_SMEM_BYTES ((QTILE + 2 * BUFSZ) * 2)   // 108544 B

__global__ __launch_bounds__(256) void attn_mma(float* __restrict__ out)
{
    extern __shared__ __half asm_[];
    const int blk = blockIdx.x;
    const int qb  = 7 - blk / 60;       // heavy tiles first
    const int t2  = blk % 60;
    const int b   = t2 / 15;
    const int cs  = t2 % 15;
    int cfg, seg;
    if (cs < 8)       { cfg = 0; seg = cs; }
    else if (cs < 12) { cfg = 1; seg = cs - 8; }
    else if (cs < 14) { cfg = 2; seg = cs - 12; }
    else              { cfg = 3; seg = 0; }
    const int rr = 1 << cfg;
    const int ww = 1024 << cfg;

    const int t = threadIdx.x;
    const int lane = t & 31;
    const int w = t >> 5;
    const size_t tok0 = (size_t)b * NN + seg * ww;

    const uint32_t sb = smem_u32(asm_);
    const uint32_t QHb = sb;

    auto kh_off = [](int buf) { return QTILE + buf * BUFSZ; };
    auto vh_off = [](int buf) { return QTILE + buf * BUFSZ + KTILE; };

    // ---- constant ones-columns in VH (cols 128..135 = 1, 136..143 = 0) ----
    for (int i = t; i < 2 * 64 * 16; i += 256) {
        int buf = i >> 10;
        int r = (i & 1023) >> 4;
        int c = i & 15;
        asm_[vh_off(buf) + r * VSTR + 128 + c] = (c < 8) ? __float2half(1.0f)
                                                         : __float2half(0.0f);
    }

    // ---- issue Q tile fill via cp.async : part of group 0 ----
    #pragma unroll
    for (int i = 0; i < 8; i++) {
        int idx = t + i * 256;
        int row = idx >> 4;
        int c = idx & 15;
        size_t src = (tok0 + (size_t)(qb * 128 + row) * rr) * NH + c * 8;
        uint32_t d = (row * ASTR + c * 8) * 2;
        cp16(QHb + d, g_qh + src);
    }

    auto issue_kv = [&](int kt, int buf) {
        #pragma unroll
        for (int i = 0; i < 4; i++) {
            int idx = t + i * 256;
            int row = idx >> 4;
            int c = idx & 15;
            size_t src = (tok0 + (size_t)(kt * 64 + row) * rr) * NH + c * 8;
            cp16(sb + (kh_off(buf) + row * ASTR + c * 8) * 2, g_kh + src);
            cp16(sb + (vh_off(buf) + row * VSTR + c * 8) * 2, g_vh + src);
        }
    };

    const int L = 2 * qb + 1;
    issue_kv(0, 0);
    cp_commit();
    issue_kv(1, 1);
    cp_commit();

    float o[16][4];
    float osum[4] = {0.f, 0.f, 0.f, 0.f};   // l accumulator (ones-column MMA)
    #pragma unroll
    for (int j = 0; j < 16; j++)
        #pragma unroll
        for (int e = 0; e < 4; e++) o[j][e] = 0.f;
    float m_i[2] = { -INFINITY, -INFINITY };

    const int lr = lane & 15;
    const int lc = (lane >> 4) * 8;

    for (int kt = 0; kt <= L; kt++) {
        if (kt < L) cp_wait<1>(); else cp_wait<0>();
        __syncthreads();

        const int buf = kt & 1;
        const uint32_t KHb = sb + kh_off(buf) * 2;
        const uint32_t VHb = sb + vh_off(buf) * 2;

        const bool active = (qb * 128 + w * 16 + 15) >= kt * 64;
        if (active) {
            // ---- S = Q @ K^T (log2 domain; 1-term) ----
            float s[8][4];
            #pragma unroll
            for (int j = 0; j < 8; j++)
                #pragma unroll
                for (int e = 0; e < 4; e++) s[j][e] = 0.f;

            #pragma unroll
            for (int ks = 0; ks < 8; ks++) {
                uint32_t qh[4];
                {
                    uint32_t off = ((w * 16 + lr) * ASTR + ks * 16 + lc) * 2;
                    ldsm_x4(qh, QHb + off);
                }
                #pragma unroll
                for (int jj = 0; jj < 4; jj++) {
                    uint32_t off = ((jj * 16 + lr) * ASTR + ks * 16 + lc) * 2;
                    uint32_t kh[4];
                    ldsm_x4(kh, KHb + off);
                    mma16816(s[2 * jj],     qh, kh[0], kh[2]);
                    mma16816(s[2 * jj + 1], qh, kh[1], kh[3]);
                }
            }

            // ---- causal mask ----
            if (kt >= 2 * qb) {
                #pragma unroll
                for (int j = 0; j < 8; j++)
                    #pragma unroll
                    for (int z = 0; z < 2; z++) {
                        int gq = qb * 128 + w * 16 + (lane >> 2) + 8 * z;
                        int gk = kt * 64 + j * 8 + 2 * (lane & 3);
                        if (gk > gq)     s[j][2 * z]     = -INFINITY;
                        if (gk + 1 > gq) s[j][2 * z + 1] = -INFINITY;
                    }
            }

            // ---- online softmax: max + rescale (exp2 domain) ----
            float mn[2];
            #pragma unroll
            for (int z = 0; z < 2; z++) {
                float mx = -INFINITY;
                #pragma unroll
                for (int j = 0; j < 8; j++)
                    mx = fmaxf(mx, fmaxf(s[j][2 * z], s[j][2 * z + 1]));
                mx = fmaxf(mx, __shfl_xor_sync(0xffffffffu, mx, 1));
                mx = fmaxf(mx, __shfl_xor_sync(0xffffffffu, mx, 2));
                mn[z] = fmaxf(m_i[z], mx);
                float sc = ex2f(m_i[z] - mn[z]);
                m_i[z] = mn[z];
                #pragma unroll
                for (int j = 0; j < 16; j++) {
                    o[j][2 * z] *= sc;
                    o[j][2 * z + 1] *= sc;
                }
                osum[2 * z] *= sc;
                osum[2 * z + 1] *= sc;
            }

            // ---- P = exp2(S - m) packed fp16x2 ----
            uint32_t p16[8][2];
            #pragma unroll
            for (int j = 0; j < 8; j++) {
                p16[j][0] = ex2_f16x2(pack_f16x2(s[j][0] - mn[0], s[j][1] - mn[0]));
                p16[j][1] = ex2_f16x2(pack_f16x2(s[j][2] - mn[1], s[j][3] - mn[1]));
            }

            // ---- O += P @ Vh (1-term) + ones-column row sums ----
            #pragma unroll
            for (int kk = 0; kk < 4; kk++) {
                const uint32_t a[4] = { p16[2 * kk][0], p16[2 * kk][1],
                                        p16[2 * kk + 1][0], p16[2 * kk + 1][1] };
                #pragma unroll
                for (int jj = 0; jj < 8; jj++) {
                    uint32_t off = ((kk * 16 + lr) * VSTR + jj * 16 + lc) * 2;
                    uint32_t vh[4];
                    ldsm_x4_t(vh, VHb + off);
                    mma16816(o[2 * jj],     a, vh[0], vh[1]);
                    mma16816(o[2 * jj + 1], a, vh[2], vh[3]);
                }
                uint32_t vs[4];
                ldsm_x4_t(vs, VHb + ((kk * 16 + lr) * VSTR + 128 + lc) * 2);
                mma16816(osum, a, vs[0], vs[1]);
            }
        }

        __syncthreads();
        if (kt + 2 <= L) {
            issue_kv(kt + 2, kt & 1);
            cp_commit();
        }
    }

    // ---- epilogue ----
    // cfg0 odd rows: alpha==1 -> direct fp32 write to out (skip g_o/g_d).
    // everything else: normalized fp16 to g_o + denom to g_d.
    const int cbase = 16384 - (16384 >> cfg);
    const size_t obase = (size_t)b * TOTROWS + cbase + seg * 1024 + qb * 128;
    #pragma unroll
    for (int z = 0; z < 2; z++) {
        const int lrow = w * 16 + (lane >> 2) + 8 * z;   // 0..127 within tile
        const size_t row = obase + lrow;
        const float l = osum[2 * z];
        const float inv = 1.0f / l;
        if (cfg == 0 && (lrow & 1)) {
            const int p = seg * 1024 + qb * 128 + lrow;  // global position (odd)
            float* orow = out + ((size_t)b * NN + p) * NH;
            #pragma unroll
            for (int j = 0; j < 16; j++) {
                const int col = j * 8 + 2 * (lane & 3);
                *(float2*)&orow[col] =
                    make_float2(o[j][2 * z] * inv, o[j][2 * z + 1] * inv);
            }
        } else {
            #pragma unroll
            for (int j = 0; j < 16; j++) {
                const int col = j * 8 + 2 * (lane & 3);
                *(uint32_t*)&g_o[row * NH + col] =
                    pack_f16x2(o[j][2 * z] * inv, o[j][2 * z + 1] * inv);
            }
            if ((lane & 3) == 0)
                g_d[row] = l * exp2f(m_i[z]);
        }
    }
}

// ---------------------------------------------------------------------------
// Kernel 3: cross-config combine over EVEN positions only (odd p written
// directly by attn). One warp per (b, even p); lane covers 4 h.
// ---------------------------------------------------------------------------
__global__ __launch_bounds__(256) void combine_kernel(float* __restrict__ out)
{
    const int gw = (blockIdx.x * blockDim.x + threadIdx.x) >> 5;
    const int lane = threadIdx.x & 31;
    if (gw >= NB * NN / 2) return;
    const int b = gw >> 12;             // 4096 even positions per batch
    const int p = (gw & 4095) * 2;
    const int c = lane * 4;

    size_t rows[4];
    float dens[4];
    int cnt = 0;
    float dsum = 0.f;
    #pragma unroll
    for (int i = 0; i < 4; i++) {
        if ((p & ((1 << i) - 1)) == 0) {
            int s = p >> (10 + i);
            int j = (p & ((1024 << i) - 1)) >> i;
            int cbase = 16384 - (16384 >> i);
            size_t row = (size_t)b * TOTROWS + cbase + s * 1024 + j;
            float d = g_d[row];
            rows[cnt] = row;
            dens[cnt] = d;
            dsum += d;
            cnt++;
        }
    }

    float4 acc = make_float4(0.f, 0.f, 0.f, 0.f);
    const float rinv = 1.0f / dsum;
    for (int q = 0; q < cnt; q++) {
        float wgt = dens[q] * rinv;
        uint2 pk = *(const uint2*)&g_o[rows[q] * NH + c];
        float2 v01 = __half22float2(*(__half2*)&pk.x);
        float2 v23 = __half22float2(*(__half2*)&pk.y);
        acc.x += v01.x * wgt;
        acc.y += v01.y * wgt;
        acc.z += v23.x * wgt;
        acc.w += v23.y * wgt;
    }
    *(float4*)&out[((size_t)b * NN + p) * NH + c] = acc;
}

// ---------------------------------------------------------------------------
extern "C" void kernel_launch(void* const* d_in, const int* in_sizes, int n_in,
                              void* d_out, int out_size)
{
    const float* x  = (const float*)d_in[0];
    const float* Wq = (const float*)d_in[1];
    const float* Wk = (const float*)d_in[2];
    const float* Wv = (const float*)d_in[3];
    float* out = (float*)d_out;

    cudaFuncSetAttribute((const void*)proj_mma,
                         cudaFuncAttributeMaxDynamicSharedMemorySize, PROJ_SMEM_BYTES);
    cudaFuncSetAttribute((const void*)attn_mma,
                         cudaFuncAttributeMaxDynamicSharedMemorySize, ATTN_SMEM_BYTES);

    split_w<<<dim3(32, 4, 3), dim3(32, 8)>>>(Wq, Wk, Wv);
    proj_mma<<<dim3(256, 3), 256, PROJ_SMEM_BYTES>>>(x);
    attn_mma<<<480, 256, ATTN_SMEM_BYTES>>>(out);
    combine_kernel<<<(NB * NN / 2 * 32 + 255) / 256, 256>>>(out);
}

// round 14
// speedup vs baseline: 1.2432x; 1.2432x over previous
#include <cuda_runtime.h>
#include <cuda_fp16.h>
#include <math.h>
#include <stdint.h>

// Problem constants
#define NB 4
#define NN 8192
#define NC 1024
#define NH 128
#define TOTROWS 15360   // 8192 + 4096 + 2048 + 1024 scratch rows per batch

// Scratch (device globals)
__device__ __half g_qh[NB * NN * NH];
__device__ __half g_kh[NB * NN * NH];
__device__ __half g_vh[NB * NN * NH];
__device__ __half g_wth[3 * 128 * 1024];   // W^T [w][n][k] fp16
__device__ __half g_o[(size_t)NB * TOTROWS * NH];
__device__ float g_d[NB * TOTROWS];

// ============================ helpers ============================
__device__ __forceinline__ uint32_t smem_u32(const void* p) {
    uint32_t a;
    asm("{ .reg .u64 t; cvta.to.shared.u64 t, %1; cvt.u32.u64 %0, t; }"
        : "=r"(a) : "l"(p));
    return a;
}

__device__ __forceinline__ void ldsm_x4(uint32_t r[4], uint32_t addr) {
    asm volatile("ldmatrix.sync.aligned.m8n8.x4.shared.b16 {%0,%1,%2,%3}, [%4];"
                 : "=r"(r[0]), "=r"(r[1]), "=r"(r[2]), "=r"(r[3]) : "r"(addr));
}
__device__ __forceinline__ void ldsm_x4_t(uint32_t r[4], uint32_t addr) {
    asm volatile("ldmatrix.sync.aligned.m8n8.x4.trans.shared.b16 {%0,%1,%2,%3}, [%4];"
                 : "=r"(r[0]), "=r"(r[1]), "=r"(r[2]), "=r"(r[3]) : "r"(addr));
}

// D(+=) A@B : m16n8k16 fp16 -> f32
__device__ __forceinline__ void mma16816(float c[4], const uint32_t a[4],
                                         uint32_t b0, uint32_t b1) {
    asm volatile(
        "mma.sync.aligned.m16n8k16.row.col.f32.f16.f16.f32 "
        "{%0,%1,%2,%3}, {%4,%5,%6,%7}, {%8,%9}, {%0,%1,%2,%3};"
        : "+f"(c[0]), "+f"(c[1]), "+f"(c[2]), "+f"(c[3])
        : "r"(a[0]), "r"(a[1]), "r"(a[2]), "r"(a[3]), "r"(b0), "r"(b1));
}

// pack two f32 (even -> low half, odd -> high half) into fp16x2
__device__ __forceinline__ uint32_t pack_f16x2(float even, float odd) {
    uint32_t d;
    asm("cvt.rn.f16x2.f32 %0, %1, %2;" : "=r"(d) : "f"(odd), "f"(even));
    return d;
}
__device__ __forceinline__ uint32_t ex2_f16x2(uint32_t a) {
    uint32_t d;
    asm("ex2.approx.f16x2 %0, %1;" : "=r"(d) : "r"(a));
    return d;
}
__device__ __forceinline__ float ex2f(float x) {
    float r;
    asm("ex2.approx.f32 %0, %1;" : "=f"(r) : "f"(x));
    return r;
}

// cp.async helpers
__device__ __forceinline__ void cp16(uint32_t dst, const void* src) {
    asm volatile("cp.async.cg.shared.global [%0], [%1], 16;" :: "r"(dst), "l"(src));
}
__device__ __forceinline__ void cp_commit() {
    asm volatile("cp.async.commit_group;" ::: "memory");
}
template <int N>
__device__ __forceinline__ void cp_wait() {
    asm volatile("cp.async.wait_group %0;" :: "n"(N) : "memory");
}

// ---------------------------------------------------------------------------
// Kernel 0: transpose W (fp16) -> g_wth [w][n=128][k=1024]
// ---------------------------------------------------------------------------
__global__ __launch_bounds__(256) void split_w(
    const float* __restrict__ Wq, const float* __restrict__ Wk,
    const float* __restrict__ Wv)
{
    __shared__ float tile[32][33];
    const float* W = (blockIdx.z == 0) ? Wq : (blockIdx.z == 1) ? Wk : Wv;
    const int k0 = blockIdx.x * 32;
    const int n0 = blockIdx.y * 32;
    const int tx = threadIdx.x, ty = threadIdx.y;
    #pragma unroll
    for (int i = ty; i < 32; i += 8)
        tile[i][tx] = W[(size_t)(k0 + i) * NH + n0 + tx];
    __syncthreads();
    #pragma unroll
    for (int i = ty; i < 32; i += 8) {
        size_t idx = (size_t)blockIdx.z * 131072 + (size_t)(n0 + i) * 1024 + k0 + tx;
        g_wth[idx] = __float2half_rn(tile[tx][i]);
    }
}

// ---------------------------------------------------------------------------
// Kernel 1: QKV projection, 1-term fp16 mma.sync: D = xh @ Wh (fp32 accum).
// CTA tile M=128, N=128, K chunks of 32. grid=(256,3) y->Wq/Wk/Wv.
// B tile loaded coalesced (uint4) from pre-transposed g_wth.
// ---------------------------------------------------------------------------
#define PSTR 40                 // padded k stride (fp16 elements)
#define PBUF (128 * PSTR)       // elements per smem array
#define PROJ_SMEM_BYTES (2 * 2 * PBUF * 2)   // 2 buffers x {AH, BH}

__global__ __launch_bounds__(256) void proj_mma(const float* __restrict__ x)
{
    extern __shared__ __half psm[];
    const int t = threadIdx.x;
    const int lane = t & 31;
    const int wid = t >> 5;
    const int wm = wid & 1;
    const int wn = wid >> 1;
    const size_t m0 = (size_t)blockIdx.x * 128;
    const int wsel = blockIdx.y;
    const __half* wth = g_wth + (size_t)wsel * 131072;

    float acc[4][4][4];
    #pragma unroll
    for (int i = 0; i < 4; i++)
        #pragma unroll
        for (int j = 0; j < 4; j++)
            #pragma unroll
            for (int e = 0; e < 4; e++) acc[i][j][e] = 0.f;

    float4 sa[4];
    uint4 sbh[2];

    const int a_row[4] = { t >> 3, (t + 256) >> 3, (t + 512) >> 3, (t + 768) >> 3 };
    const int a_c4 = (t & 7) * 4;

    auto load_stage = [&](int k0) {
        #pragma unroll
        for (int p = 0; p < 4; p++)
            sa[p] = *(const float4*)&x[(m0 + a_row[p]) * NC + k0 + a_c4];
        #pragma unroll
        for (int p = 0; p < 2; p++) {
            int idx = t + p * 256;
            int row = idx >> 2, c8 = idx & 3;
            sbh[p] = *(const uint4*)&wth[(size_t)row * 1024 + k0 + c8 * 8];
        }
    };
    auto store_stage = [&](int buf) {
        __half* AH = psm + buf * 2 * PBUF;
        __half* BH = AH + PBUF;
        #pragma unroll
        for (int p = 0; p < 4; p++) {
            uint32_t h01 = pack_f16x2(sa[p].x, sa[p].y);
            uint32_t h23 = pack_f16x2(sa[p].z, sa[p].w);
            uint32_t off = a_row[p] * PSTR + a_c4;
            *(uint2*)&AH[off] = make_uint2(h01, h23);
        }
        #pragma unroll
        for (int p = 0; p < 2; p++) {
            int idx = t + p * 256;
            int row = idx >> 2, c8 = idx & 3;
            *(uint4*)&BH[row * PSTR + c8 * 8] = sbh[p];
        }
    };

    const uint32_t smbase = smem_u32(psm);
    const int lr = lane & 15;
    const int lc = (lane >> 4) * 8;

    auto compute = [&](int buf) {
        const uint32_t AHb = smbase + (buf * 2 * PBUF) * 2;
        const uint32_t BHb = AHb + PBUF * 2;
        #pragma unroll
        for (int ks = 0; ks < 2; ks++) {
            uint32_t ah[4][4];
            #pragma unroll
            for (int i = 0; i < 4; i++) {
                uint32_t off = ((wm * 64 + i * 16 + lr) * PSTR + ks * 16 + lc) * 2;
                ldsm_x4(ah[i], AHb + off);
            }
            #pragma unroll
            for (int jj = 0; jj < 2; jj++) {
                uint32_t off = ((wn * 32 + jj * 16 + lr) * PSTR + ks * 16 + lc) * 2;
                uint32_t bh[4];
                ldsm_x4(bh, BHb + off);
                #pragma unroll
                for (int i = 0; i < 4; i++) {
                    mma16816(acc[i][2 * jj],     ah[i], bh[0], bh[2]);
                    mma16816(acc[i][2 * jj + 1], ah[i], bh[1], bh[3]);
                }
            }
        }
    };

    load_stage(0);
    for (int c = 0; c < 32; c++) {
        store_stage(c & 1);
        __syncthreads();
        if (c + 1 < 32) load_stage((c + 1) * 32);
        compute(c & 1);
    }

    // epilogue: q pre-scaled by log2(e)/sqrt(128); single fp16 store
    const float scale = (wsel == 0) ? (0.08838834764831843f * 1.4426950408889634f) : 1.0f;
    __half* DH = (wsel == 0) ? g_qh : (wsel == 1) ? g_kh : g_vh;
    #pragma unroll
    for (int i = 0; i < 4; i++) {
        #pragma unroll
        for (int j = 0; j < 4; j++) {
            const int col = wn * 32 + j * 8 + 2 * (lane & 3);
            #pragma unroll
            for (int z = 0; z < 2; z++) {
                const size_t row = m0 + wm * 64 + i * 16 + (lane >> 2) + 8 * z;
                *(uint32_t*)&DH[row * NH + col] =
                    pack_f16x2(acc[i][j][2 * z] * scale, acc[i][j][2 * z + 1] * scale);
            }
        }
    }
}

// ---------------------------------------------------------------------------
// Kernel 2: causal flash attention, fp16 mma.sync, packed-fp16 exp2 softmax.
// QK 1-term, PV 1-term. 128-row Q tiles, 8 warps, cp.async double buffering.
// Warp-tile-granularity causal skipping only (uniform per-warp branch; finer
// runtime predication regressed scheduling in R11/R13).
// V carries 8 constant ones-columns (cols 128..135) -> row-sums via MMA.
// ---------------------------------------------------------------------------
#define ASTR 136                        // Q/K padded stride (fp16 elems)
#define VSTR 152                        // V padded stride (128 data + 16 ones/pad)
#define QTILE (128 * ASTR)              // 17408
#define KTILE (64 * ASTR)               // 8704
#define VTILE (64 * VSTR)               // 9728
#define BUFSZ (KTILE + VTILE)           // 18432 elems per buffer
#define ATTN_SMEM_BYTES ((QTILE + 2 * BUFSZ) * 2)   // 108544 B

__global__ __launch_bounds__(256) void attn_mma()
{
    extern __shared__ __half asm_[];
    const int blk = blockIdx.x;
    const int qb  = 7 - blk / 60;       // heavy tiles first
    const int t2  = blk % 60;
    const int b   = t2 / 15;
    const int cs  = t2 % 15;
    int cfg, seg;
    if (cs < 8)       { cfg = 0; seg = cs; }
    else if (cs < 12) { cfg = 1; seg = cs - 8; }
    else if (cs < 14) { cfg = 2; seg = cs - 12; }
    else              { cfg = 3; seg = 0; }
    const int rr = 1 << cfg;
    const int ww = 1024 << cfg;

    const int t = threadIdx.x;
    const int lane = t & 31;
    const int w = t >> 5;
    const size_t tok0 = (size_t)b * NN + seg * ww;

    const uint32_t sb = smem_u32(asm_);
    const uint32_t QHb = sb;

    auto kh_off = [](int buf) { return QTILE + buf * BUFSZ; };
    auto vh_off = [](int buf) { return QTILE + buf * BUFSZ + KTILE; };

    // ---- constant ones-columns in VH (cols 128..135 = 1, 136..143 = 0) ----
    for (int i = t; i < 2 * 64 * 16; i += 256) {
        int buf = i >> 10;
        int r = (i & 1023) >> 4;
        int c = i & 15;
        asm_[vh_off(buf) + r * VSTR + 128 + c] = (c < 8) ? __float2half(1.0f)
                                                         : __float2half(0.0f);
    }

    // ---- issue Q tile fill via cp.async : part of group 0 ----
    #pragma unroll
    for (int i = 0; i < 8; i++) {
        int idx = t + i * 256;
        int row = idx >> 4;
        int c = idx & 15;
        size_t src = (tok0 + (size_t)(qb * 128 + row) * rr) * NH + c * 8;
        uint32_t d = (row * ASTR + c * 8) * 2;
        cp16(QHb + d, g_qh + src);
    }

    auto issue_kv = [&](int kt, int buf) {
        #pragma unroll
        for (int i = 0; i < 4; i++) {
            int idx = t + i * 256;
            int row = idx >> 4;
            int c = idx & 15;
            size_t src = (tok0 + (size_t)(kt * 64 + row) * rr) * NH + c * 8;
            cp16(sb + (kh_off(buf) + row * ASTR + c * 8) * 2, g_kh + src);
            cp16(sb + (vh_off(buf) + row * VSTR + c * 8) * 2, g_vh + src);
        }
    };

    const int L = 2 * qb + 1;
    issue_kv(0, 0);
    cp_commit();
    issue_kv(1, 1);
    cp_commit();

    float o[16][4];
    float osum[4] = {0.f, 0.f, 0.f, 0.f};   // l accumulator (ones-column MMA)
    #pragma unroll
    for (int j = 0; j < 16; j++)
        #pragma unroll
        for (int e = 0; e < 4; e++) o[j][e] = 0.f;
    float m_i[2] = { -INFINITY, -INFINITY };

    const int lr = lane & 15;
    const int lc = (lane >> 4) * 8;

    for (int kt = 0; kt <= L; kt++) {
        if (kt < L) cp_wait<1>(); else cp_wait<0>();
        __syncthreads();

        const int buf = kt & 1;
        const uint32_t KHb = sb + kh_off(buf) * 2;
        const uint32_t VHb = sb + vh_off(buf) * 2;

        const bool active = (qb * 128 + w * 16 + 15) >= kt * 64;
        if (active) {
            // ---- S = Q @ K^T (log2 domain; 1-term) ----
            float s[8][4];
            #pragma unroll
            for (int j = 0; j < 8; j++)
                #pragma unroll
                for (int e = 0; e < 4; e++) s[j][e] = 0.f;

            #pragma unroll
            for (int ks = 0; ks < 8; ks++) {
                uint32_t qh[4];
                {
                    uint32_t off = ((w * 16 + lr) * ASTR + ks * 16 + lc) * 2;
                    ldsm_x4(qh, QHb + off);
                }
                #pragma unroll
                for (int jj = 0; jj < 4; jj++) {
                    uint32_t off = ((jj * 16 + lr) * ASTR + ks * 16 + lc) * 2;
                    uint32_t kh[4];
                    ldsm_x4(kh, KHb + off);
                    mma16816(s[2 * jj],     qh, kh[0], kh[2]);
                    mma16816(s[2 * jj + 1], qh, kh[1], kh[3]);
                }
            }

            // ---- causal mask ----
            if (kt >= 2 * qb) {
                #pragma unroll
                for (int j = 0; j < 8; j++)
                    #pragma unroll
                    for (int z = 0; z < 2; z++) {
                        int gq = qb * 128 + w * 16 + (lane >> 2) + 8 * z;
                        int gk = kt * 64 + j * 8 + 2 * (lane & 3);
                        if (gk > gq)     s[j][2 * z]     = -INFINITY;
                        if (gk + 1 > gq) s[j][2 * z + 1] = -INFINITY;
                    }
            }

            // ---- online softmax: max + rescale (exp2 domain) ----
            float mn[2];
            #pragma unroll
            for (int z = 0; z < 2; z++) {
                float mx = -INFINITY;
                #pragma unroll
                for (int j = 0; j < 8; j++)
                    mx = fmaxf(mx, fmaxf(s[j][2 * z], s[j][2 * z + 1]));
                mx = fmaxf(mx, __shfl_xor_sync(0xffffffffu, mx, 1));
                mx = fmaxf(mx, __shfl_xor_sync(0xffffffffu, mx, 2));
                mn[z] = fmaxf(m_i[z], mx);
                float sc = ex2f(m_i[z] - mn[z]);
                m_i[z] = mn[z];
                #pragma unroll
                for (int j = 0; j < 16; j++) {
                    o[j][2 * z] *= sc;
                    o[j][2 * z + 1] *= sc;
                }
                osum[2 * z] *= sc;
                osum[2 * z + 1] *= sc;
            }

            // ---- P = exp2(S - m) packed fp16x2 ----
            uint32_t p16[8][2];
            #pragma unroll
            for (int j = 0; j < 8; j++) {
                p16[j][0] = ex2_f16x2(pack_f16x2(s[j][0] - mn[0], s[j][1] - mn[0]));
                p16[j][1] = ex2_f16x2(pack_f16x2(s[j][2] - mn[1], s[j][3] - mn[1]));
            }

            // ---- O += P @ Vh (1-term) + ones-column row sums ----
            #pragma unroll
            for (int kk = 0; kk < 4; kk++) {
                const uint32_t a[4] = { p16[2 * kk][0], p16[2 * kk][1],
                                        p16[2 * kk + 1][0], p16[2 * kk + 1][1] };
                #pragma unroll
                for (int jj = 0; jj < 8; jj++) {
                    uint32_t off = ((kk * 16 + lr) * VSTR + jj * 16 + lc) * 2;
                    uint32_t vh[4];
                    ldsm_x4_t(vh, VHb + off);
                    mma16816(o[2 * jj],     a, vh[0], vh[1]);
                    mma16816(o[2 * jj + 1], a, vh[2], vh[3]);
                }
                uint32_t vs[4];
                ldsm_x4_t(vs, VHb + ((kk * 16 + lr) * VSTR + 128 + lc) * 2);
                mma16816(osum, a, vs[0], vs[1]);
            }
        }

        __syncthreads();
        if (kt + 2 <= L) {
            issue_kv(kt + 2, kt & 1);
            cp_commit();
        }
    }

    // ---- epilogue: normalize, write o (fp16) and denom = l * 2^m ----
    const int cbase = 16384 - (16384 >> cfg);
    const size_t obase = (size_t)b * TOTROWS + cbase + seg * 1024 + qb * 128;
    #pragma unroll
    for (int z = 0; z < 2; z++) {
        const size_t row = obase + w * 16 + (lane >> 2) + 8 * z;
        const float l = osum[2 * z];
        const float inv = 1.0f / l;
        #pragma unroll
        for (int j = 0; j < 16; j++) {
            const int col = j * 8 + 2 * (lane & 3);
            *(uint32_t*)&g_o[row * NH + col] =
                pack_f16x2(o[j][2 * z] * inv, o[j][2 * z + 1] * inv);
        }
        if ((lane & 3) == 0)
            g_d[row] = l * exp2f(m_i[z]);
    }
}

// ---------------------------------------------------------------------------
// Kernel 3: cross-config combine. One warp per (b, p); lane covers 4 h.
// Odd p appear only in cfg0 -> alpha == 1 -> pure convert-copy fast path.
// ---------------------------------------------------------------------------
__global__ __launch_bounds__(256) void combine_kernel(float* __restrict__ out)
{
    const int gw = (blockIdx.x * blockDim.x + threadIdx.x) >> 5;
    const int lane = threadIdx.x & 31;
    if (gw >= NB * NN) return;
    const int b = gw >> 13;
    const int p = gw & (NN - 1);
    const int c = lane * 4;

    if (p & 1) {   // cnt == 1: alpha = denom/denom = 1
        const size_t row = (size_t)b * TOTROWS + p;   // cfg0, cbase=0
        uint2 pk = *(const uint2*)&g_o[row * NH + c];
        float2 v01 = __half22float2(*(__half2*)&pk.x);
        float2 v23 = __half22float2(*(__half2*)&pk.y);
        *(float4*)&out[((size_t)b * NN + p) * NH + c] =
            make_float4(v01.x, v01.y, v23.x, v23.y);
        return;
    }

    size_t rows[4];
    float dens[4];
    int cnt = 0;
    float dsum = 0.f;
    #pragma unroll
    for (int i = 0; i < 4; i++) {
        if ((p & ((1 << i) - 1)) == 0) {
            int s = p >> (10 + i);
            int j = (p & ((1024 << i) - 1)) >> i;
            int cbase = 16384 - (16384 >> i);
            size_t row = (size_t)b * TOTROWS + cbase + s * 1024 + j;
            float d = g_d[row];
            rows[cnt] = row;
            dens[cnt] = d;
            dsum += d;
            cnt++;
        }
    }

    float4 acc = make_float4(0.f, 0.f, 0.f, 0.f);
    const float rinv = 1.0f / dsum;
    for (int q = 0; q < cnt; q++) {
        float wgt = dens[q] * rinv;
        uint2 pk = *(const uint2*)&g_o[rows[q] * NH + c];
        float2 v01 = __half22float2(*(__half2*)&pk.x);
        float2 v23 = __half22float2(*(__half2*)&pk.y);
        acc.x += v01.x * wgt;
        acc.y += v01.y * wgt;
        acc.z += v23.x * wgt;
        acc.w += v23.y * wgt;
    }
    *(float4*)&out[((size_t)b * NN + p) * NH + c] = acc;
}

// ---------------------------------------------------------------------------
extern "C" void kernel_launch(void* const* d_in, const int* in_sizes, int n_in,
                              void* d_out, int out_size)
{
    const float* x  = (const float*)d_in[0];
    const float* Wq = (const float*)d_in[1];
    const float* Wk = (const float*)d_in[2];
    const float* Wv = (const float*)d_in[3];
    float* out = (float*)d_out;

    cudaFuncSetAttribute((const void*)proj_mma,
                         cudaFuncAttributeMaxDynamicSharedMemorySize, PROJ_SMEM_BYTES);
    cudaFuncSetAttribute((const void*)attn_mma,
                         cudaFuncAttributeMaxDynamicSharedMemorySize, ATTN_SMEM_BYTES);

    split_w<<<dim3(32, 4, 3), dim3(32, 8)>>>(Wq, Wk, Wv);
    proj_mma<<<dim3(256, 3), 256, PROJ_SMEM_BYTES>>>(x);
    attn_mma<<<480, 256, ATTN_SMEM_BYTES>>>();
    combine_kernel<<<(NB * NN * 32 + 255) / 256, 256>>>(out);
}

// round 15
// speedup vs baseline: 1.2541x; 1.0088x over previous
#include <cuda_runtime.h>
#include <cuda_fp16.h>
#include <math.h>
#include <stdint.h>

// Problem constants
#define NB 4
#define NN 8192
#define NC 1024
#define NH 128
#define TOTROWS 15360   // 8192 + 4096 + 2048 + 1024 scratch rows per batch

// Scratch (device globals)
__device__ __half g_qh[NB * NN * NH];
__device__ __half g_kh[NB * NN * NH];
__device__ __half g_vh[NB * NN * NH];
__device__ __half g_wth[3 * 128 * 1024];   // W^T [w][n][k] fp16
__device__ __half g_o[(size_t)NB * TOTROWS * NH];
__device__ float g_d[NB * TOTROWS];

// ============================ helpers ============================
__device__ __forceinline__ uint32_t smem_u32(const void* p) {
    uint32_t a;
    asm("{ .reg .u64 t; cvta.to.shared.u64 t, %1; cvt.u32.u64 %0, t; }"
        : "=r"(a) : "l"(p));
    return a;
}

__device__ __forceinline__ void ldsm_x4(uint32_t r[4], uint32_t addr) {
    asm volatile("ldmatrix.sync.aligned.m8n8.x4.shared.b16 {%0,%1,%2,%3}, [%4];"
                 : "=r"(r[0]), "=r"(r[1]), "=r"(r[2]), "=r"(r[3]) : "r"(addr));
}
__device__ __forceinline__ void ldsm_x4_t(uint32_t r[4], uint32_t addr) {
    asm volatile("ldmatrix.sync.aligned.m8n8.x4.trans.shared.b16 {%0,%1,%2,%3}, [%4];"
                 : "=r"(r[0]), "=r"(r[1]), "=r"(r[2]), "=r"(r[3]) : "r"(addr));
}

// D(+=) A@B : m16n8k16 fp16 -> f32
__device__ __forceinline__ void mma16816(float c[4], const uint32_t a[4],
                                         uint32_t b0, uint32_t b1) {
    asm volatile(
        "mma.sync.aligned.m16n8k16.row.col.f32.f16.f16.f32 "
        "{%0,%1,%2,%3}, {%4,%5,%6,%7}, {%8,%9}, {%0,%1,%2,%3};"
        : "+f"(c[0]), "+f"(c[1]), "+f"(c[2]), "+f"(c[3])
        : "r"(a[0]), "r"(a[1]), "r"(a[2]), "r"(a[3]), "r"(b0), "r"(b1));
}

// pack two f32 (even -> low half, odd -> high half) into fp16x2
__device__ __forceinline__ uint32_t pack_f16x2(float even, float odd) {
    uint32_t d;
    asm("cvt.rn.f16x2.f32 %0, %1, %2;" : "=r"(d) : "f"(odd), "f"(even));
    return d;
}
__device__ __forceinline__ uint32_t ex2_f16x2(uint32_t a) {
    uint32_t d;
    asm("ex2.approx.f16x2 %0, %1;" : "=r"(d) : "r"(a));
    return d;
}
__device__ __forceinline__ float ex2f(float x) {
    float r;
    asm("ex2.approx.f32 %0, %1;" : "=f"(r) : "f"(x));
    return r;
}

// cp.async helpers
__device__ __forceinline__ void cp16(uint32_t dst, const void* src) {
    asm volatile("cp.async.cg.shared.global [%0], [%1], 16;" :: "r"(dst), "l"(src));
}
__device__ __forceinline__ void cp_commit() {
    asm volatile("cp.async.commit_group;" ::: "memory");
}
template <int N>
__device__ __forceinline__ void cp_wait() {
    asm volatile("cp.async.wait_group %0;" :: "n"(N) : "memory");
}

// ---------------------------------------------------------------------------
// Kernel 0: transpose W (fp16) -> g_wth [w][n=128][k=1024]
// ---------------------------------------------------------------------------
__global__ __launch_bounds__(256) void split_w(
    const float* __restrict__ Wq, const float* __restrict__ Wk,
    const float* __restrict__ Wv)
{
    __shared__ float tile[32][33];
    const float* W = (blockIdx.z == 0) ? Wq : (blockIdx.z == 1) ? Wk : Wv;
    const int k0 = blockIdx.x * 32;
    const int n0 = blockIdx.y * 32;
    const int tx = threadIdx.x, ty = threadIdx.y;
    #pragma unroll
    for (int i = ty; i < 32; i += 8)
        tile[i][tx] = W[(size_t)(k0 + i) * NH + n0 + tx];
    __syncthreads();
    #pragma unroll
    for (int i = ty; i < 32; i += 8) {
        size_t idx = (size_t)blockIdx.z * 131072 + (size_t)(n0 + i) * 1024 + k0 + tx;
        g_wth[idx] = __float2half_rn(tile[tx][i]);
    }
}

// ---------------------------------------------------------------------------
// Kernel 1: QKV projection, 1-term fp16 mma.sync: D = xh @ Wh (fp32 accum).
// CTA tile M=128, N=128, K chunks of 32. grid=(256,3) y->Wq/Wk/Wv.
// B tile loaded coalesced (uint4) from pre-transposed g_wth.
// ---------------------------------------------------------------------------
#define PSTR 40                 // padded k stride (fp16 elements)
#define PBUF (128 * PSTR)       // elements per smem array
#define PROJ_SMEM_BYTES (2 * 2 * PBUF * 2)   // 2 buffers x {AH, BH}

__global__ __launch_bounds__(256) void proj_mma(const float* __restrict__ x)
{
    extern __shared__ __half psm[];
    const int t = threadIdx.x;
    const int lane = t & 31;
    const int wid = t >> 5;
    const int wm = wid & 1;
    const int wn = wid >> 1;
    const size_t m0 = (size_t)blockIdx.x * 128;
    const int wsel = blockIdx.y;
    const __half* wth = g_wth + (size_t)wsel * 131072;

    float acc[4][4][4];
    #pragma unroll
    for (int i = 0; i < 4; i++)
        #pragma unroll
        for (int j = 0; j < 4; j++)
            #pragma unroll
            for (int e = 0; e < 4; e++) acc[i][j][e] = 0.f;

    float4 sa[4];
    uint4 sbh[2];

    const int a_row[4] = { t >> 3, (t + 256) >> 3, (t + 512) >> 3, (t + 768) >> 3 };
    const int a_c4 = (t & 7) * 4;

    auto load_stage = [&](int k0) {
        #pragma unroll
        for (int p = 0; p < 4; p++)
            sa[p] = *(const float4*)&x[(m0 + a_row[p]) * NC + k0 + a_c4];
        #pragma unroll
        for (int p = 0; p < 2; p++) {
            int idx = t + p * 256;
            int row = idx >> 2, c8 = idx & 3;
            sbh[p] = *(const uint4*)&wth[(size_t)row * 1024 + k0 + c8 * 8];
        }
    };
    auto store_stage = [&](int buf) {
        __half* AH = psm + buf * 2 * PBUF;
        __half* BH = AH + PBUF;
        #pragma unroll
        for (int p = 0; p < 4; p++) {
            uint32_t h01 = pack_f16x2(sa[p].x, sa[p].y);
            uint32_t h23 = pack_f16x2(sa[p].z, sa[p].w);
            uint32_t off = a_row[p] * PSTR + a_c4;
            *(uint2*)&AH[off] = make_uint2(h01, h23);
        }
        #pragma unroll
        for (int p = 0; p < 2; p++) {
            int idx = t + p * 256;
            int row = idx >> 2, c8 = idx & 3;
            *(uint4*)&BH[row * PSTR + c8 * 8] = sbh[p];
        }
    };

    const uint32_t smbase = smem_u32(psm);
    const int lr = lane & 15;
    const int lc = (lane >> 4) * 8;

    auto compute = [&](int buf) {
        const uint32_t AHb = smbase + (buf * 2 * PBUF) * 2;
        const uint32_t BHb = AHb + PBUF * 2;
        #pragma unroll
        for (int ks = 0; ks < 2; ks++) {
            uint32_t ah[4][4];
            #pragma unroll
            for (int i = 0; i < 4; i++) {
                uint32_t off = ((wm * 64 + i * 16 + lr) * PSTR + ks * 16 + lc) * 2;
                ldsm_x4(ah[i], AHb + off);
            }
            #pragma unroll
            for (int jj = 0; jj < 2; jj++) {
                uint32_t off = ((wn * 32 + jj * 16 + lr) * PSTR + ks * 16 + lc) * 2;
                uint32_t bh[4];
                ldsm_x4(bh, BHb + off);
                #pragma unroll
                for (int i = 0; i < 4; i++) {
                    mma16816(acc[i][2 * jj],     ah[i], bh[0], bh[2]);
                    mma16816(acc[i][2 * jj + 1], ah[i], bh[1], bh[3]);
                }
            }
        }
    };

    load_stage(0);
    for (int c = 0; c < 32; c++) {
        store_stage(c & 1);
        __syncthreads();
        if (c + 1 < 32) load_stage((c + 1) * 32);
        compute(c & 1);
    }

    // epilogue: q pre-scaled by log2(e)/sqrt(128); single fp16 store
    const float scale = (wsel == 0) ? (0.08838834764831843f * 1.4426950408889634f) : 1.0f;
    __half* DH = (wsel == 0) ? g_qh : (wsel == 1) ? g_kh : g_vh;
    #pragma unroll
    for (int i = 0; i < 4; i++) {
        #pragma unroll
        for (int j = 0; j < 4; j++) {
            const int col = wn * 32 + j * 8 + 2 * (lane & 3);
            #pragma unroll
            for (int z = 0; z < 2; z++) {
                const size_t row = m0 + wm * 64 + i * 16 + (lane >> 2) + 8 * z;
                *(uint32_t*)&DH[row * NH + col] =
                    pack_f16x2(acc[i][j][2 * z] * scale, acc[i][j][2 * z + 1] * scale);
            }
        }
    }
}

// ---------------------------------------------------------------------------
// Kernel 2: causal flash attention, fp16 mma.sync, packed-fp16 exp2 softmax.
// QK 1-term, PV 1-term. 256-row Q tiles, 16 warps (512 thr), cp.async
// double-buffered 64-row K/V. Same warp-level numeric sequence as the
// 128-row version (identical 64-key tile order per row) -> bit-identical.
// K/V fills per segment drop 72 -> 40; barrier count nearly halves.
// V carries 8 constant ones-columns (cols 128..135) -> row-sums via MMA.
// ---------------------------------------------------------------------------
#define ASTR 136                        // Q/K padded stride (fp16 elems)
#define VSTR 152                        // V padded stride (128 data + 16 ones/pad)
#define QTILE (256 * ASTR)              // 34816
#define KTILE (64 * ASTR)               // 8704
#define VTILE (64 * VSTR)               // 9728
#define BUFSZ (KTILE + VTILE)           // 18432 elems per buffer
#define ATTN_SMEM_BYTES ((QTILE + 2 * BUFSZ) * 2)   // 143360 B

__global__ __launch_bounds__(512) void attn_mma()
{
    extern __shared__ __half asm_[];
    const int blk = blockIdx.x;
    const int qb  = 3 - blk / 60;       // 256-row q tile index, heavy first
    const int t2  = blk % 60;
    const int b   = t2 / 15;
    const int cs  = t2 % 15;
    int cfg, seg;
    if (cs < 8)       { cfg = 0; seg = cs; }
    else if (cs < 12) { cfg = 1; seg = cs - 8; }
    else if (cs < 14) { cfg = 2; seg = cs - 12; }
    else              { cfg = 3; seg = 0; }
    const int rr = 1 << cfg;
    const int ww = 1024 << cfg;

    const int t = threadIdx.x;
    const int lane = t & 31;
    const int w = t >> 5;               // warp id 0..15: q rows w*16..w*16+15
    const size_t tok0 = (size_t)b * NN + seg * ww;

    const uint32_t sb = smem_u32(asm_);
    const uint32_t QHb = sb;

    auto kh_off = [](int buf) { return QTILE + buf * BUFSZ; };
    auto vh_off = [](int buf) { return QTILE + buf * BUFSZ + KTILE; };

    // ---- constant ones-columns in VH (cols 128..135 = 1, 136..143 = 0) ----
    for (int i = t; i < 2 * 64 * 16; i += 512) {
        int buf = i >> 10;
        int r = (i & 1023) >> 4;
        int c = i & 15;
        asm_[vh_off(buf) + r * VSTR + 128 + c] = (c < 8) ? __float2half(1.0f)
                                                         : __float2half(0.0f);
    }

    // ---- issue Q tile fill (256 rows) via cp.async : part of group 0 ----
    #pragma unroll
    for (int i = 0; i < 8; i++) {
        int idx = t + i * 512;           // 0..4095
        int row = idx >> 4;              // 0..255
        int c = idx & 15;
        size_t src = (tok0 + (size_t)(qb * 256 + row) * rr) * NH + c * 8;
        uint32_t d = (row * ASTR + c * 8) * 2;
        cp16(QHb + d, g_qh + src);
    }

    auto issue_kv = [&](int kt, int buf) {
        #pragma unroll
        for (int i = 0; i < 2; i++) {
            int idx = t + i * 512;        // 0..1023
            int row = idx >> 4;           // 0..63
            int c = idx & 15;
            size_t src = (tok0 + (size_t)(kt * 64 + row) * rr) * NH + c * 8;
            cp16(sb + (kh_off(buf) + row * ASTR + c * 8) * 2, g_kh + src);
            cp16(sb + (vh_off(buf) + row * VSTR + c * 8) * 2, g_vh + src);
        }
    };

    const int L = 4 * qb + 3;            // last 64-key tile index
    issue_kv(0, 0);
    cp_commit();
    issue_kv(1, 1);
    cp_commit();

    float o[16][4];
    float osum[4] = {0.f, 0.f, 0.f, 0.f};   // l accumulator (ones-column MMA)
    #pragma unroll
    for (int j = 0; j < 16; j++)
        #pragma unroll
        for (int e = 0; e < 4; e++) o[j][e] = 0.f;
    float m_i[2] = { -INFINITY, -INFINITY };

    const int lr = lane & 15;
    const int lc = (lane >> 4) * 8;

    for (int kt = 0; kt <= L; kt++) {
        if (kt < L) cp_wait<1>(); else cp_wait<0>();
        __syncthreads();

        const int buf = kt & 1;
        const uint32_t KHb = sb + kh_off(buf) * 2;
        const uint32_t VHb = sb + vh_off(buf) * 2;

        const bool active = (qb * 256 + w * 16 + 15) >= kt * 64;
        if (active) {
            // ---- S = Q @ K^T (log2 domain; 1-term) ----
            float s[8][4];
            #pragma unroll
            for (int j = 0; j < 8; j++)
                #pragma unroll
                for (int e = 0; e < 4; e++) s[j][e] = 0.f;

            #pragma unroll
            for (int ks = 0; ks < 8; ks++) {
                uint32_t qh[4];
                {
                    uint32_t off = ((w * 16 + lr) * ASTR + ks * 16 + lc) * 2;
                    ldsm_x4(qh, QHb + off);
                }
                #pragma unroll
                for (int jj = 0; jj < 4; jj++) {
                    uint32_t off = ((jj * 16 + lr) * ASTR + ks * 16 + lc) * 2;
                    uint32_t kh[4];
                    ldsm_x4(kh, KHb + off);
                    mma16816(s[2 * jj],     qh, kh[0], kh[2]);
                    mma16816(s[2 * jj + 1], qh, kh[1], kh[3]);
                }
            }

            // ---- causal mask (diagonal band: last 4 kt tiles of this q tile) ----
            if (kt >= 4 * qb) {
                #pragma unroll
                for (int j = 0; j < 8; j++)
                    #pragma unroll
                    for (int z = 0; z < 2; z++) {
                        int gq = qb * 256 + w * 16 + (lane >> 2) + 8 * z;
                        int gk = kt * 64 + j * 8 + 2 * (lane & 3);
                        if (gk > gq)     s[j][2 * z]     = -INFINITY;
                        if (gk + 1 > gq) s[j][2 * z + 1] = -INFINITY;
                    }
            }

            // ---- online softmax: max + rescale (exp2 domain) ----
            float mn[2];
            #pragma unroll
            for (int z = 0; z < 2; z++) {
                float mx = -INFINITY;
                #pragma unroll
                for (int j = 0; j < 8; j++)
                    mx = fmaxf(mx, fmaxf(s[j][2 * z], s[j][2 * z + 1]));
                mx = fmaxf(mx, __shfl_xor_sync(0xffffffffu, mx, 1));
                mx = fmaxf(mx, __shfl_xor_sync(0xffffffffu, mx, 2));
                mn[z] = fmaxf(m_i[z], mx);
                float sc = ex2f(m_i[z] - mn[z]);
                m_i[z] = mn[z];
                #pragma unroll
                for (int j = 0; j < 16; j++) {
                    o[j][2 * z] *= sc;
                    o[j][2 * z + 1] *= sc;
                }
                osum[2 * z] *= sc;
                osum[2 * z + 1] *= sc;
            }

            // ---- P = exp2(S - m) packed fp16x2 ----
            uint32_t p16[8][2];
            #pragma unroll
            for (int j = 0; j < 8; j++) {
                p16[j][0] = ex2_f16x2(pack_f16x2(s[j][0] - mn[0], s[j][1] - mn[0]));
                p16[j][1] = ex2_f16x2(pack_f16x2(s[j][2] - mn[1], s[j][3] - mn[1]));
            }

            // ---- O += P @ Vh (1-term) + ones-column row sums ----
            #pragma unroll
            for (int kk = 0; kk < 4; kk++) {
                const uint32_t a[4] = { p16[2 * kk][0], p16[2 * kk][1],
                                        p16[2 * kk + 1][0], p16[2 * kk + 1][1] };
                #pragma unroll
                for (int jj = 0; jj < 8; jj++) {
                    uint32_t off = ((kk * 16 + lr) * VSTR + jj * 16 + lc) * 2;
                    uint32_t vh[4];
                    ldsm_x4_t(vh, VHb + off);
                    mma16816(o[2 * jj],     a, vh[0], vh[1]);
                    mma16816(o[2 * jj + 1], a, vh[2], vh[3]);
                }
                uint32_t vs[4];
                ldsm_x4_t(vs, VHb + ((kk * 16 + lr) * VSTR + 128 + lc) * 2);
                mma16816(osum, a, vs[0], vs[1]);
            }
        }

        __syncthreads();
        if (kt + 2 <= L) {
            issue_kv(kt + 2, kt & 1);
            cp_commit();
        }
    }

    // ---- epilogue: normalize, write o (fp16) and denom = l * 2^m ----
    const int cbase = 16384 - (16384 >> cfg);
    const size_t obase = (size_t)b * TOTROWS + cbase + seg * 1024 + qb * 256;
    #pragma unroll
    for (int z = 0; z < 2; z++) {
        const size_t row = obase + w * 16 + (lane >> 2) + 8 * z;
        const float l = osum[2 * z];
        const float inv = 1.0f / l;
        #pragma unroll
        for (int j = 0; j < 16; j++) {
            const int col = j * 8 + 2 * (lane & 3);
            *(uint32_t*)&g_o[row * NH + col] =
                pack_f16x2(o[j][2 * z] * inv, o[j][2 * z + 1] * inv);
        }
        if ((lane & 3) == 0)
            g_d[row] = l * exp2f(m_i[z]);
    }
}

// ---------------------------------------------------------------------------
// Kernel 3: cross-config combine. One warp per (b, p); lane covers 4 h.
// Odd p appear only in cfg0 -> alpha == 1 -> pure convert-copy fast path.
// ---------------------------------------------------------------------------
__global__ __launch_bounds__(256) void combine_kernel(float* __restrict__ out)
{
    const int gw = (blockIdx.x * blockDim.x + threadIdx.x) >> 5;
    const int lane = threadIdx.x & 31;
    if (gw >= NB * NN) return;
    const int b = gw >> 13;
    const int p = gw & (NN - 1);
    const int c = lane * 4;

    if (p & 1) {   // cnt == 1: alpha = denom/denom = 1
        const size_t row = (size_t)b * TOTROWS + p;   // cfg0, cbase=0
        uint2 pk = *(const uint2*)&g_o[row * NH + c];
        float2 v01 = __half22float2(*(__half2*)&pk.x);
        float2 v23 = __half22float2(*(__half2*)&pk.y);
        *(float4*)&out[((size_t)b * NN + p) * NH + c] =
            make_float4(v01.x, v01.y, v23.x, v23.y);
        return;
    }

    size_t rows[4];
    float dens[4];
    int cnt = 0;
    float dsum = 0.f;
    #pragma unroll
    for (int i = 0; i < 4; i++) {
        if ((p & ((1 << i) - 1)) == 0) {
            int s = p >> (10 + i);
            int j = (p & ((1024 << i) - 1)) >> i;
            int cbase = 16384 - (16384 >> i);
            size_t row = (size_t)b * TOTROWS + cbase + s * 1024 + j;
            float d = g_d[row];
            rows[cnt] = row;
            dens[cnt] = d;
            dsum += d;
            cnt++;
        }
    }

    float4 acc = make_float4(0.f, 0.f, 0.f, 0.f);
    const float rinv = 1.0f / dsum;
    for (int q = 0; q < cnt; q++) {
        float wgt = dens[q] * rinv;
        uint2 pk = *(const uint2*)&g_o[rows[q] * NH + c];
        float2 v01 = __half22float2(*(__half2*)&pk.x);
        float2 v23 = __half22float2(*(__half2*)&pk.y);
        acc.x += v01.x * wgt;
        acc.y += v01.y * wgt;
        acc.z += v23.x * wgt;
        acc.w += v23.y * wgt;
    }
    *(float4*)&out[((size_t)b * NN + p) * NH + c] = acc;
}

// ---------------------------------------------------------------------------
extern "C" void kernel_launch(void* const* d_in, const int* in_sizes, int n_in,
                              void* d_out, int out_size)
{
    const float* x  = (const float*)d_in[0];
    const float* Wq = (const float*)d_in[1];
    const float* Wk = (const float*)d_in[2];
    const float* Wv = (const float*)d_in[3];
    float* out = (float*)d_out;

    cudaFuncSetAttribute((const void*)proj_mma,
                         cudaFuncAttributeMaxDynamicSharedMemorySize, PROJ_SMEM_BYTES);
    cudaFuncSetAttribute((const void*)attn_mma,
                         cudaFuncAttributeMaxDynamicSharedMemorySize, ATTN_SMEM_BYTES);

    split_w<<<dim3(32, 4, 3), dim3(32, 8)>>>(Wq, Wk, Wv);
    proj_mma<<<dim3(256, 3), 256, PROJ_SMEM_BYTES>>>(x);
    attn_mma<<<240, 512, ATTN_SMEM_BYTES>>>();
    combine_kernel<<<(NB * NN * 32 + 255) / 256, 256>>>(out);
}

// round 16
// speedup vs baseline: 1.2744x; 1.0161x over previous
#include <cuda_runtime.h>
#include <cuda_fp16.h>
#include <math.h>
#include <stdint.h>

// Problem constants
#define NB 4
#define NN 8192
#define NC 1024
#define NH 128
#define TOTROWS 15360   // 8192 + 4096 + 2048 + 1024 scratch rows per batch

// Scratch (device globals)
__device__ __half g_qh[NB * NN * NH];
__device__ __half g_kh[NB * NN * NH];
__device__ __half g_vh[NB * NN * NH];
__device__ __half g_wth[3 * 128 * 1024];   // W^T [w][n][k] fp16
__device__ __half g_o[(size_t)NB * TOTROWS * NH];
__device__ float g_d[NB * TOTROWS];

// ============================ helpers ============================
__device__ __forceinline__ uint32_t smem_u32(const void* p) {
    uint32_t a;
    asm("{ .reg .u64 t; cvta.to.shared.u64 t, %1; cvt.u32.u64 %0, t; }"
        : "=r"(a) : "l"(p));
    return a;
}

__device__ __forceinline__ void ldsm_x4(uint32_t r[4], uint32_t addr) {
    asm volatile("ldmatrix.sync.aligned.m8n8.x4.shared.b16 {%0,%1,%2,%3}, [%4];"
                 : "=r"(r[0]), "=r"(r[1]), "=r"(r[2]), "=r"(r[3]) : "r"(addr));
}
__device__ __forceinline__ void ldsm_x4_t(uint32_t r[4], uint32_t addr) {
    asm volatile("ldmatrix.sync.aligned.m8n8.x4.trans.shared.b16 {%0,%1,%2,%3}, [%4];"
                 : "=r"(r[0]), "=r"(r[1]), "=r"(r[2]), "=r"(r[3]) : "r"(addr));
}

// D(+=) A@B : m16n8k16 fp16 -> f32
__device__ __forceinline__ void mma16816(float c[4], const uint32_t a[4],
                                         uint32_t b0, uint32_t b1) {
    asm volatile(
        "mma.sync.aligned.m16n8k16.row.col.f32.f16.f16.f32 "
        "{%0,%1,%2,%3}, {%4,%5,%6,%7}, {%8,%9}, {%0,%1,%2,%3};"
        : "+f"(c[0]), "+f"(c[1]), "+f"(c[2]), "+f"(c[3])
        : "r"(a[0]), "r"(a[1]), "r"(a[2]), "r"(a[3]), "r"(b0), "r"(b1));
}

// pack two f32 (even -> low half, odd -> high half) into fp16x2
__device__ __forceinline__ uint32_t pack_f16x2(float even, float odd) {
    uint32_t d;
    asm("cvt.rn.f16x2.f32 %0, %1, %2;" : "=r"(d) : "f"(odd), "f"(even));
    return d;
}
__device__ __forceinline__ uint32_t ex2_f16x2(uint32_t a) {
    uint32_t d;
    asm("ex2.approx.f16x2 %0, %1;" : "=r"(d) : "r"(a));
    return d;
}
__device__ __forceinline__ float ex2f(float x) {
    float r;
    asm("ex2.approx.f32 %0, %1;" : "=f"(r) : "f"(x));
    return r;
}

// cp.async helpers
__device__ __forceinline__ void cp16(uint32_t dst, const void* src) {
    asm volatile("cp.async.cg.shared.global [%0], [%1], 16;" :: "r"(dst), "l"(src));
}
__device__ __forceinline__ void cp_commit() {
    asm volatile("cp.async.commit_group;" ::: "memory");
}
template <int N>
__device__ __forceinline__ void cp_wait() {
    asm volatile("cp.async.wait_group %0;" :: "n"(N) : "memory");
}

// ---------------------------------------------------------------------------
// Kernel 0: transpose W (fp16) -> g_wth [w][n=128][k=1024]
// ---------------------------------------------------------------------------
__global__ __launch_bounds__(256) void split_w(
    const float* __restrict__ Wq, const float* __restrict__ Wk,
    const float* __restrict__ Wv)
{
    __shared__ float tile[32][33];
    const float* W = (blockIdx.z == 0) ? Wq : (blockIdx.z == 1) ? Wk : Wv;
    const int k0 = blockIdx.x * 32;
    const int n0 = blockIdx.y * 32;
    const int tx = threadIdx.x, ty = threadIdx.y;
    #pragma unroll
    for (int i = ty; i < 32; i += 8)
        tile[i][tx] = W[(size_t)(k0 + i) * NH + n0 + tx];
    __syncthreads();
    #pragma unroll
    for (int i = ty; i < 32; i += 8) {
        size_t idx = (size_t)blockIdx.z * 131072 + (size_t)(n0 + i) * 1024 + k0 + tx;
        g_wth[idx] = __float2half_rn(tile[tx][i]);
    }
}

// ---------------------------------------------------------------------------
// Kernel 1: QKV projection, 1-term fp16 mma.sync: D = xh @ Wh (fp32 accum).
// CTA tile M=128, N=128, K chunks of 32. grid=(256,3) y->Wq/Wk/Wv.
// B tile loaded coalesced (uint4) from pre-transposed g_wth.
// ---------------------------------------------------------------------------
#define PSTR 40                 // padded k stride (fp16 elements)
#define PBUF (128 * PSTR)       // elements per smem array
#define PROJ_SMEM_BYTES (2 * 2 * PBUF * 2)   // 2 buffers x {AH, BH}

__global__ __launch_bounds__(256) void proj_mma(const float* __restrict__ x)
{
    extern __shared__ __half psm[];
    const int t = threadIdx.x;
    const int lane = t & 31;
    const int wid = t >> 5;
    const int wm = wid & 1;
    const int wn = wid >> 1;
    const size_t m0 = (size_t)blockIdx.x * 128;
    const int wsel = blockIdx.y;
    const __half* wth = g_wth + (size_t)wsel * 131072;

    float acc[4][4][4];
    #pragma unroll
    for (int i = 0; i < 4; i++)
        #pragma unroll
        for (int j = 0; j < 4; j++)
            #pragma unroll
            for (int e = 0; e < 4; e++) acc[i][j][e] = 0.f;

    float4 sa[4];
    uint4 sbh[2];

    const int a_row[4] = { t >> 3, (t + 256) >> 3, (t + 512) >> 3, (t + 768) >> 3 };
    const int a_c4 = (t & 7) * 4;

    auto load_stage = [&](int k0) {
        #pragma unroll
        for (int p = 0; p < 4; p++)
            sa[p] = *(const float4*)&x[(m0 + a_row[p]) * NC + k0 + a_c4];
        #pragma unroll
        for (int p = 0; p < 2; p++) {
            int idx = t + p * 256;
            int row = idx >> 2, c8 = idx & 3;
            sbh[p] = *(const uint4*)&wth[(size_t)row * 1024 + k0 + c8 * 8];
        }
    };
    auto store_stage = [&](int buf) {
        __half* AH = psm + buf * 2 * PBUF;
        __half* BH = AH + PBUF;
        #pragma unroll
        for (int p = 0; p < 4; p++) {
            uint32_t h01 = pack_f16x2(sa[p].x, sa[p].y);
            uint32_t h23 = pack_f16x2(sa[p].z, sa[p].w);
            uint32_t off = a_row[p] * PSTR + a_c4;
            *(uint2*)&AH[off] = make_uint2(h01, h23);
        }
        #pragma unroll
        for (int p = 0; p < 2; p++) {
            int idx = t + p * 256;
            int row = idx >> 2, c8 = idx & 3;
            *(uint4*)&BH[row * PSTR + c8 * 8] = sbh[p];
        }
    };

    const uint32_t smbase = smem_u32(psm);
    const int lr = lane & 15;
    const int lc = (lane >> 4) * 8;

    auto compute = [&](int buf) {
        const uint32_t AHb = smbase + (buf * 2 * PBUF) * 2;
        const uint32_t BHb = AHb + PBUF * 2;
        #pragma unroll
        for (int ks = 0; ks < 2; ks++) {
            uint32_t ah[4][4];
            #pragma unroll
            for (int i = 0; i < 4; i++) {
                uint32_t off = ((wm * 64 + i * 16 + lr) * PSTR + ks * 16 + lc) * 2;
                ldsm_x4(ah[i], AHb + off);
            }
            #pragma unroll
            for (int jj = 0; jj < 2; jj++) {
                uint32_t off = ((wn * 32 + jj * 16 + lr) * PSTR + ks * 16 + lc) * 2;
                uint32_t bh[4];
                ldsm_x4(bh, BHb + off);
                #pragma unroll
                for (int i = 0; i < 4; i++) {
                    mma16816(acc[i][2 * jj],     ah[i], bh[0], bh[2]);
                    mma16816(acc[i][2 * jj + 1], ah[i], bh[1], bh[3]);
                }
            }
        }
    };

    load_stage(0);
    for (int c = 0; c < 32; c++) {
        store_stage(c & 1);
        __syncthreads();
        if (c + 1 < 32) load_stage((c + 1) * 32);
        compute(c & 1);
    }

    // epilogue: q pre-scaled by log2(e)/sqrt(128); single fp16 store
    const float scale = (wsel == 0) ? (0.08838834764831843f * 1.4426950408889634f) : 1.0f;
    __half* DH = (wsel == 0) ? g_qh : (wsel == 1) ? g_kh : g_vh;
    #pragma unroll
    for (int i = 0; i < 4; i++) {
        #pragma unroll
        for (int j = 0; j < 4; j++) {
            const int col = wn * 32 + j * 8 + 2 * (lane & 3);
            #pragma unroll
            for (int z = 0; z < 2; z++) {
                const size_t row = m0 + wm * 64 + i * 16 + (lane >> 2) + 8 * z;
                *(uint32_t*)&DH[row * NH + col] =
                    pack_f16x2(acc[i][j][2 * z] * scale, acc[i][j][2 * z + 1] * scale);
            }
        }
    }
}

// ---------------------------------------------------------------------------
// Kernel 2: causal flash attention, fp16 mma.sync, packed-fp16 exp2 softmax.
// QK 1-term, PV 1-term. 256-row Q tiles, 16 warps (512 thr), cp.async
// double-buffered 64-row K/V. Warp-tile-granularity causal skipping.
// V carries 8 constant ones-columns (cols 128..135) -> row-sums via MMA.
// ---------------------------------------------------------------------------
#define ASTR 136                        // Q/K padded stride (fp16 elems)
#define VSTR 152                        // V padded stride (128 data + 16 ones/pad)
#define QTILE (256 * ASTR)              // 34816
#define KTILE (64 * ASTR)               // 8704
#define VTILE (64 * VSTR)               // 9728
#define BUFSZ (KTILE + VTILE)           // 18432 elems per buffer
#define ATTN_SMEM_BYTES ((QTILE + 2 * BUFSZ) * 2)   // 143360 B

__global__ __launch_bounds__(512) void attn_mma()
{
    extern __shared__ __half asm_[];
    const int blk = blockIdx.x;
    const int qb  = 3 - blk / 60;       // 256-row q tile index, heavy first
    const int t2  = blk % 60;
    const int b   = t2 / 15;
    const int cs  = t2 % 15;
    int cfg, seg;
    if (cs < 8)       { cfg = 0; seg = cs; }
    else if (cs < 12) { cfg = 1; seg = cs - 8; }
    else if (cs < 14) { cfg = 2; seg = cs - 12; }
    else              { cfg = 3; seg = 0; }
    const int rr = 1 << cfg;
    const int ww = 1024 << cfg;

    const int t = threadIdx.x;
    const int lane = t & 31;
    const int w = t >> 5;               // warp id 0..15: q rows w*16..w*16+15
    const size_t tok0 = (size_t)b * NN + seg * ww;

    const uint32_t sb = smem_u32(asm_);
    const uint32_t QHb = sb;

    auto kh_off = [](int buf) { return QTILE + buf * BUFSZ; };
    auto vh_off = [](int buf) { return QTILE + buf * BUFSZ + KTILE; };

    // ---- constant ones-columns in VH (cols 128..135 = 1, 136..143 = 0) ----
    for (int i = t; i < 2 * 64 * 16; i += 512) {
        int buf = i >> 10;
        int r = (i & 1023) >> 4;
        int c = i & 15;
        asm_[vh_off(buf) + r * VSTR + 128 + c] = (c < 8) ? __float2half(1.0f)
                                                         : __float2half(0.0f);
    }

    // ---- issue Q tile fill (256 rows) via cp.async : part of group 0 ----
    #pragma unroll
    for (int i = 0; i < 8; i++) {
        int idx = t + i * 512;           // 0..4095
        int row = idx >> 4;              // 0..255
        int c = idx & 15;
        size_t src = (tok0 + (size_t)(qb * 256 + row) * rr) * NH + c * 8;
        uint32_t d = (row * ASTR + c * 8) * 2;
        cp16(QHb + d, g_qh + src);
    }

    auto issue_kv = [&](int kt, int buf) {
        #pragma unroll
        for (int i = 0; i < 2; i++) {
            int idx = t + i * 512;        // 0..1023
            int row = idx >> 4;           // 0..63
            int c = idx & 15;
            size_t src = (tok0 + (size_t)(kt * 64 + row) * rr) * NH + c * 8;
            cp16(sb + (kh_off(buf) + row * ASTR + c * 8) * 2, g_kh + src);
            cp16(sb + (vh_off(buf) + row * VSTR + c * 8) * 2, g_vh + src);
        }
    };

    const int L = 4 * qb + 3;            // last 64-key tile index
    issue_kv(0, 0);
    cp_commit();
    issue_kv(1, 1);
    cp_commit();

    float o[16][4];
    float osum[4] = {0.f, 0.f, 0.f, 0.f};   // l accumulator (ones-column MMA)
    #pragma unroll
    for (int j = 0; j < 16; j++)
        #pragma unroll
        for (int e = 0; e < 4; e++) o[j][e] = 0.f;
    float m_i[2] = { -INFINITY, -INFINITY };

    const int lr = lane & 15;
    const int lc = (lane >> 4) * 8;

    for (int kt = 0; kt <= L; kt++) {
        if (kt < L) cp_wait<1>(); else cp_wait<0>();
        __syncthreads();

        const int buf = kt & 1;
        const uint32_t KHb = sb + kh_off(buf) * 2;
        const uint32_t VHb = sb + vh_off(buf) * 2;

        const bool active = (qb * 256 + w * 16 + 15) >= kt * 64;
        if (active) {
            // ---- S = Q @ K^T (log2 domain; 1-term) ----
            float s[8][4];
            #pragma unroll
            for (int j = 0; j < 8; j++)
                #pragma unroll
                for (int e = 0; e < 4; e++) s[j][e] = 0.f;

            #pragma unroll
            for (int ks = 0; ks < 8; ks++) {
                uint32_t qh[4];
                {
                    uint32_t off = ((w * 16 + lr) * ASTR + ks * 16 + lc) * 2;
                    ldsm_x4(qh, QHb + off);
                }
                #pragma unroll
                for (int jj = 0; jj < 4; jj++) {
                    uint32_t off = ((jj * 16 + lr) * ASTR + ks * 16 + lc) * 2;
                    uint32_t kh[4];
                    ldsm_x4(kh, KHb + off);
                    mma16816(s[2 * jj],     qh, kh[0], kh[2]);
                    mma16816(s[2 * jj + 1], qh, kh[1], kh[3]);
                }
            }

            // ---- causal mask (diagonal band: last 4 kt tiles of this q tile) ----
            if (kt >= 4 * qb) {
                #pragma unroll
                for (int j = 0; j < 8; j++)
                    #pragma unroll
                    for (int z = 0; z < 2; z++) {
                        int gq = qb * 256 + w * 16 + (lane >> 2) + 8 * z;
                        int gk = kt * 64 + j * 8 + 2 * (lane & 3);
                        if (gk > gq)     s[j][2 * z]     = -INFINITY;
                        if (gk + 1 > gq) s[j][2 * z + 1] = -INFINITY;
                    }
            }

            // ---- online softmax: max + rescale (exp2 domain) ----
            float mn[2];
            #pragma unroll
            for (int z = 0; z < 2; z++) {
                float mx = -INFINITY;
                #pragma unroll
                for (int j = 0; j < 8; j++)
                    mx = fmaxf(mx, fmaxf(s[j][2 * z], s[j][2 * z + 1]));
                mx = fmaxf(mx, __shfl_xor_sync(0xffffffffu, mx, 1));
                mx = fmaxf(mx, __shfl_xor_sync(0xffffffffu, mx, 2));
                mn[z] = fmaxf(m_i[z], mx);
                float sc = ex2f(m_i[z] - mn[z]);
                m_i[z] = mn[z];
                #pragma unroll
                for (int j = 0; j < 16; j++) {
                    o[j][2 * z] *= sc;
                    o[j][2 * z + 1] *= sc;
                }
                osum[2 * z] *= sc;
                osum[2 * z + 1] *= sc;
            }

            // ---- P = exp2(S - m) packed fp16x2 ----
            uint32_t p16[8][2];
            #pragma unroll
            for (int j = 0; j < 8; j++) {
                p16[j][0] = ex2_f16x2(pack_f16x2(s[j][0] - mn[0], s[j][1] - mn[0]));
                p16[j][1] = ex2_f16x2(pack_f16x2(s[j][2] - mn[1], s[j][3] - mn[1]));
            }

            // ---- O += P @ Vh (1-term) + ones-column row sums ----
            #pragma unroll
            for (int kk = 0; kk < 4; kk++) {
                const uint32_t a[4] = { p16[2 * kk][0], p16[2 * kk][1],
                                        p16[2 * kk + 1][0], p16[2 * kk + 1][1] };
                #pragma unroll
                for (int jj = 0; jj < 8; jj++) {
                    uint32_t off = ((kk * 16 + lr) * VSTR + jj * 16 + lc) * 2;
                    uint32_t vh[4];
                    ldsm_x4_t(vh, VHb + off);
                    mma16816(o[2 * jj],     a, vh[0], vh[1]);
                    mma16816(o[2 * jj + 1], a, vh[2], vh[3]);
                }
                uint32_t vs[4];
                ldsm_x4_t(vs, VHb + ((kk * 16 + lr) * VSTR + 128 + lc) * 2);
                mma16816(osum, a, vs[0], vs[1]);
            }
        }

        __syncthreads();
        if (kt + 2 <= L) {
            issue_kv(kt + 2, kt & 1);
            cp_commit();
        }
    }

    // ---- epilogue: normalize, write o (fp16) and denom = l * 2^m ----
    const int cbase = 16384 - (16384 >> cfg);
    const size_t obase = (size_t)b * TOTROWS + cbase + seg * 1024 + qb * 256;
    #pragma unroll
    for (int z = 0; z < 2; z++) {
        const size_t row = obase + w * 16 + (lane >> 2) + 8 * z;
        const float l = osum[2 * z];
        const float inv = 1.0f / l;
        #pragma unroll
        for (int j = 0; j < 16; j++) {
            const int col = j * 8 + 2 * (lane & 3);
            *(uint32_t*)&g_o[row * NH + col] =
                pack_f16x2(o[j][2 * z] * inv, o[j][2 * z + 1] * inv);
        }
        if ((lane & 3) == 0)
            g_d[row] = l * exp2f(m_i[z]);
    }
}

// ---------------------------------------------------------------------------
// Kernel 3: cross-config combine. One warp per (b, p); lane covers 4 h.
// Odd p: single-config fast path (alpha == 1 -> convert-copy).
// Even p: FIXED 4-slot loop with zero-weight inactive slots; all g_o loads
// hoisted before the weighted sum for memory-level parallelism. Inactive
// slots contribute exactly +0.0f to dsum and acc -> bit-identical output.
// ---------------------------------------------------------------------------
__global__ __launch_bounds__(256) void combine_kernel(float* __restrict__ out)
{
    const int gw = (blockIdx.x * blockDim.x + threadIdx.x) >> 5;
    const int lane = threadIdx.x & 31;
    if (gw >= NB * NN) return;
    const int b = gw >> 13;
    const int p = gw & (NN - 1);
    const int c = lane * 4;

    if (p & 1) {   // cnt == 1: alpha = denom/denom = 1
        const size_t row = (size_t)b * TOTROWS + p;   // cfg0, cbase=0
        uint2 pk = *(const uint2*)&g_o[row * NH + c];
        float2 v01 = __half22float2(*(__half2*)&pk.x);
        float2 v23 = __half22float2(*(__half2*)&pk.y);
        *(float4*)&out[((size_t)b * NN + p) * NH + c] =
            make_float4(v01.x, v01.y, v23.x, v23.y);
        return;
    }

    // fixed 4 slots; inactive slots: row 0, weight 0 (exact no-op)
    size_t rows[4];
    float dens[4];
    #pragma unroll
    for (int i = 0; i < 4; i++) {
        const bool act = (p & ((1 << i) - 1)) == 0;
        int s = p >> (10 + i);
        int j = (p & ((1024 << i) - 1)) >> i;
        int cbase = 16384 - (16384 >> i);
        size_t row = (size_t)b * TOTROWS + cbase + s * 1024 + j;
        rows[i] = act ? row : 0;
        dens[i] = act ? g_d[rows[i]] : 0.f;
    }
    float dsum = ((dens[0] + dens[1]) + dens[2]) + dens[3];

    // hoist all g_o loads (independent -> MLP)
    uint2 pk[4];
    #pragma unroll
    for (int i = 0; i < 4; i++)
        pk[i] = *(const uint2*)&g_o[rows[i] * NH + c];

    float4 acc = make_float4(0.f, 0.f, 0.f, 0.f);
    const float rinv = 1.0f / dsum;
    #pragma unroll
    for (int i = 0; i < 4; i++) {
        float wgt = dens[i] * rinv;
        float2 v01 = __half22float2(*(__half2*)&pk[i].x);
        float2 v23 = __half22float2(*(__half2*)&pk[i].y);
        acc.x += v01.x * wgt;
        acc.y += v01.y * wgt;
        acc.z += v23.x * wgt;
        acc.w += v23.y * wgt;
    }
    *(float4*)&out[((size_t)b * NN + p) * NH + c] = acc;
}

// ---------------------------------------------------------------------------
extern "C" void kernel_launch(void* const* d_in, const int* in_sizes, int n_in,
                              void* d_out, int out_size)
{
    const float* x  = (const float*)d_in[0];
    const float* Wq = (const float*)d_in[1];
    const float* Wk = (const float*)d_in[2];
    const float* Wv = (const float*)d_in[3];
    float* out = (float*)d_out;

    cudaFuncSetAttribute((const void*)proj_mma,
                         cudaFuncAttributeMaxDynamicSharedMemorySize, PROJ_SMEM_BYTES);
    cudaFuncSetAttribute((const void*)attn_mma,
                         cudaFuncAttributeMaxDynamicSharedMemorySize, ATTN_SMEM_BYTES);

    split_w<<<dim3(32, 4, 3), dim3(32, 8)>>>(Wq, Wk, Wv);
    proj_mma<<<dim3(256, 3), 256, PROJ_SMEM_BYTES>>>(x);
    attn_mma<<<240, 512, ATTN_SMEM_BYTES>>>();
    combine_kernel<<<(NB * NN * 32 + 255) / 256, 256>>>(out);
}